// round 1
// baseline (speedup 1.0000x reference)
#include <cuda_runtime.h>
#include <cstdint>
#include <cmath>

// Problem constants: M=8 modalities, D=256, B=8192.
// Pipeline:
//   E[s,t]   = Wo[s,t] @ Wv[s,t]            (64 x 256^3 GEMM, scaled 1/7, diag=0)
//   cross[s] = Xcat @ Efold[s]^T + cbias[s]  (B x 256 x K=2048)
//   hid[m]   = relu([x[m],cross[m]] @ W1[m]^T + b1[m])
//   fused[m] = hid[m] @ W2[m]^T + b2[m]
//   ch[m]    = relu([q,fused[m]] @ Wc1^T + bc1)
//   out[b]   = mean_m sigmoid(ch[m,b].wc2 + bc2) * fused[m,b]

// ---------------- scratch (device globals; no cudaMalloc allowed) ----------
__device__ __align__(256) float g_WvT  [64 * 256 * 256];         // 16 MB
__device__ __align__(256) float g_Efold[8 * 256 * 2048];         // 16 MB
__device__ __align__(256) float g_Xcat [(size_t)8192 * 2048];    // 64 MB
__device__ __align__(256) float g_cbias[8 * 256];
__device__ __align__(256) float g_cross[(size_t)8 * 8192 * 256]; // 64 MB
__device__ __align__(256) float g_hid  [(size_t)8 * 8192 * 256]; // 64 MB
__device__ __align__(256) float g_fused[(size_t)8 * 8192 * 256]; // 64 MB
__device__ __align__(256) float g_ch   [(size_t)8 * 8192 * 256]; // 64 MB

// ---------------- helper kernels ------------------------------------------

// WvT[p][d][e] = Wv[p][e][d] for p in [0,64)
__global__ void transpose_wv(const float* __restrict__ Wv, float* __restrict__ WvT) {
    __shared__ float tile[32][33];
    int p = blockIdx.z;
    const float* src = Wv + (size_t)p * 65536;
    float* dst = WvT + (size_t)p * 65536;
    int x0 = blockIdx.x * 32, y0 = blockIdx.y * 32;
    for (int j = threadIdx.y; j < 32; j += 8)
        tile[j][threadIdx.x] = src[(size_t)(y0 + j) * 256 + x0 + threadIdx.x];
    __syncthreads();
    for (int j = threadIdx.y; j < 32; j += 8)
        dst[(size_t)(x0 + j) * 256 + y0 + threadIdx.x] = tile[threadIdx.x][j];
}

// Xcat[b][t*256+d] = x[t][b][d]   (float4 granularity)
__global__ void build_xcat(const float* __restrict__ x, float* __restrict__ Xcat) {
    size_t i = (size_t)blockIdx.x * blockDim.x + threadIdx.x; // over 4,194,304 float4
    int d4 = (int)(i & 63);
    size_t r = i >> 6;
    int b = (int)(r & 8191);
    int t = (int)(r >> 13);
    float4 v = reinterpret_cast<const float4*>(x)[((size_t)t * 8192 + b) * 64 + d4];
    reinterpret_cast<float4*>(Xcat)[((size_t)b * 8 + t) * 64 + d4] = v;
}

// cbias[s][o] = (1/7) * sum_{t != s} ( sum_e Wo[s,t,o,e]*bv[s,t,e] + bo[s,t,o] )
__global__ void cbias_kernel(const float* __restrict__ Wo, const float* __restrict__ bv,
                             const float* __restrict__ bo, float* __restrict__ cbias) {
    int s = blockIdx.x;
    int o = threadIdx.x;
    float acc = 0.f;
    for (int t = 0; t < 8; t++) {
        if (t == s) continue;
        size_t p = (size_t)(s * 8 + t);
        const float* wrow = Wo + (p * 256 + o) * 256;
        const float* bvp  = bv + p * 256;
        float tmp = bo[p * 256 + o];
        for (int e = 0; e < 256; e++) tmp += wrow[e] * bvp[e];
        acc += tmp;
    }
    cbias[s * 256 + o] = acc * (1.f / 7.f);
}

// ---------------- generic NT SGEMM: C = act(alpha * A·B^T + bias) ----------
// A(r,k) = k<k_split ? A0[(r % amod0)*lda0 + k] : A1[r*lda1 + (k-k_split)]
// B is [N x K] row-major (ldb). Tiles: BM=BN=128, BK=8, 256 threads, 8x8/thread.
// All dims assumed multiples of tile sizes (true for this problem).
__global__ void __launch_bounds__(256) sgemm_nt(
    const float* __restrict__ A0, long a0_batch, int lda0, int amod0,
    const float* __restrict__ A1, long a1_batch, int lda1, int k_split,
    const float* __restrict__ Bm, long b_batch, int ldb,
    const float* __restrict__ bias, long bias_batch,
    float* __restrict__ C, long c_batch, long c_batch2, int zdiv,
    int ldc, int K, float alpha, int diag_mode, int relu) {

    int z = blockIdx.z;
    int zq = z / zdiv, zr = z - zq * zdiv;
    float aeff = (diag_mode && zq == zr) ? 0.f : alpha;
    const float* A0p = A0 + (size_t)z * a0_batch;
    const float* A1p = A1 + (size_t)z * a1_batch;
    const float* Bp  = Bm + (size_t)z * b_batch;
    const float* biasp = bias ? (bias + (size_t)z * bias_batch) : nullptr;
    float* Cp = C + (size_t)zq * c_batch + (size_t)zr * c_batch2;

    __shared__ float As[8][128];
    __shared__ float Bs[8][128];

    int tid = threadIdx.x;
    int lrow = tid >> 1;            // 0..127
    int lk = (tid & 1) << 2;        // 0 or 4
    int row0 = blockIdx.y * 128;
    int col0 = blockIdx.x * 128;
    int growA = row0 + lrow;
    int nrowB = col0 + lrow;
    int tx = tid & 15, ty = tid >> 4;

    float acc[8][8];
#pragma unroll
    for (int i = 0; i < 8; i++)
#pragma unroll
        for (int j = 0; j < 8; j++) acc[i][j] = 0.f;

    for (int k0 = 0; k0 < K; k0 += 8) {
        float4 av, bvec;
        if (k0 < k_split) {
            int ar = growA % amod0;
            av = *reinterpret_cast<const float4*>(A0p + (size_t)ar * lda0 + (k0 + lk));
        } else {
            av = *reinterpret_cast<const float4*>(A1p + (size_t)growA * lda1 + (k0 - k_split + lk));
        }
        bvec = *reinterpret_cast<const float4*>(Bp + (size_t)nrowB * ldb + (k0 + lk));
        As[lk + 0][lrow] = av.x; As[lk + 1][lrow] = av.y;
        As[lk + 2][lrow] = av.z; As[lk + 3][lrow] = av.w;
        Bs[lk + 0][lrow] = bvec.x; Bs[lk + 1][lrow] = bvec.y;
        Bs[lk + 2][lrow] = bvec.z; Bs[lk + 3][lrow] = bvec.w;
        __syncthreads();
#pragma unroll
        for (int kk = 0; kk < 8; kk++) {
            float ra[8], rb[8];
#pragma unroll
            for (int i = 0; i < 8; i++) ra[i] = As[kk][ty * 8 + i];
#pragma unroll
            for (int j = 0; j < 8; j++) rb[j] = Bs[kk][tx * 8 + j];
#pragma unroll
            for (int i = 0; i < 8; i++)
#pragma unroll
                for (int j = 0; j < 8; j++) acc[i][j] += ra[i] * rb[j];
        }
        __syncthreads();
    }

#pragma unroll
    for (int i = 0; i < 8; i++) {
        size_t r = (size_t)row0 + ty * 8 + i;
#pragma unroll
        for (int j = 0; j < 8; j++) {
            int c = col0 + tx * 8 + j;
            float v = acc[i][j] * aeff;
            if (biasp) v += biasp[c];
            if (relu) v = fmaxf(v, 0.f);
            Cp[r * (size_t)ldc + c] = v;
        }
    }
}

// ---------------- final gating + mean over modalities ----------------------
__global__ void final_gate(const float* __restrict__ ch, const float* __restrict__ fused,
                           const float* __restrict__ wc2, const float* __restrict__ bc2,
                           float* __restrict__ out) {
    int b = blockIdx.x;
    int tid = threadIdx.x;
    int m = tid >> 5, lane = tid & 31;
    __shared__ float ssc[8];

    const float* chrow = ch + ((size_t)m * 8192 + b) * 256;
    float p = 0.f;
#pragma unroll
    for (int j = 0; j < 8; j++) {
        int d = lane + j * 32;
        p += chrow[d] * wc2[d];
    }
#pragma unroll
    for (int off = 16; off; off >>= 1) p += __shfl_xor_sync(0xffffffffu, p, off);
    if (lane == 0) ssc[m] = 1.f / (1.f + expf(-(p + bc2[0])));
    __syncthreads();

    int o = tid;
    float acc = 0.f;
#pragma unroll
    for (int mm = 0; mm < 8; mm++)
        acc += ssc[mm] * fused[((size_t)mm * 8192 + b) * 256 + o];
    out[(size_t)b * 256 + o] = acc * 0.125f;
}

// ---------------- launch ---------------------------------------------------
extern "C" void kernel_launch(void* const* d_in, const int* in_sizes, int n_in,
                              void* d_out, int out_size) {
    const float* x   = (const float*)d_in[0];
    const float* rq  = (const float*)d_in[1];
    const float* Wv  = (const float*)d_in[2];
    const float* bv  = (const float*)d_in[3];
    const float* Wo  = (const float*)d_in[4];
    const float* bo  = (const float*)d_in[5];
    const float* W1  = (const float*)d_in[6];
    const float* b1  = (const float*)d_in[7];
    const float* W2  = (const float*)d_in[8];
    const float* b2  = (const float*)d_in[9];
    const float* Wc1 = (const float*)d_in[10];
    const float* bc1 = (const float*)d_in[11];
    const float* wc2 = (const float*)d_in[12];
    const float* bc2 = (const float*)d_in[13];
    float* out = (float*)d_out;

    static float *pWvT = nullptr, *pEfold, *pXcat, *pcbias, *pcross, *phid, *pfused, *pch;
    if (!pWvT) {
        cudaGetSymbolAddress((void**)&pWvT,   g_WvT);
        cudaGetSymbolAddress((void**)&pEfold, g_Efold);
        cudaGetSymbolAddress((void**)&pXcat,  g_Xcat);
        cudaGetSymbolAddress((void**)&pcbias, g_cbias);
        cudaGetSymbolAddress((void**)&pcross, g_cross);
        cudaGetSymbolAddress((void**)&phid,   g_hid);
        cudaGetSymbolAddress((void**)&pfused, g_fused);
        cudaGetSymbolAddress((void**)&pch,    g_ch);
    }

    // 1) WvT per (s,t) pair
    transpose_wv<<<dim3(8, 8, 64), dim3(32, 8)>>>(Wv, pWvT);
    // 2) Xcat[b, t*256+d]
    build_xcat<<<4194304 / 256, 256>>>(x, pXcat);
    // 3) cbias
    cbias_kernel<<<8, 256>>>(Wo, bv, bo, pcbias);
    // 4) Efold[s][o][t*256+d] = (s!=t) * (1/7) * (Wo[s,t] @ Wv[s,t])[o][d]
    //    z = s*8+t; C offset = (z/8)*524288 + (z%8)*256
    sgemm_nt<<<dim3(2, 2, 64), 256>>>(
        Wo, 65536, 256, 256,  nullptr, 0, 0, 256,
        pWvT, 65536, 256,  nullptr, 0,
        pEfold, 524288, 256, 8,  2048, 256, 1.f / 7.f, 1, 0);
    // 5) cross[s] = Xcat @ Efold[s]^T + cbias[s]
    sgemm_nt<<<dim3(2, 64, 8), 256>>>(
        pXcat, 0, 2048, 8192,  nullptr, 0, 0, 2048,
        pEfold, 524288, 2048,  pcbias, 256,
        pcross, 2097152, 0, 1,  256, 2048, 1.f, 0, 0);
    // 6) hid[m] = relu([x[m], cross[m]] @ W1[m]^T + b1[m])
    sgemm_nt<<<dim3(2, 64, 8), 256>>>(
        x, 2097152, 256, 8192,  pcross, 2097152, 256, 256,
        W1, 131072, 512,  b1, 256,
        phid, 2097152, 0, 1,  256, 512, 1.f, 0, 1);
    // 7) fused[m] = hid[m] @ W2[m]^T + b2[m]
    sgemm_nt<<<dim3(2, 64, 8), 256>>>(
        phid, 2097152, 256, 8192,  nullptr, 0, 0, 256,
        W2, 65536, 256,  b2, 256,
        pfused, 2097152, 0, 1,  256, 256, 1.f, 0, 0);
    // 8) ch = relu([q (broadcast over m), fused] @ Wc1^T + bc1), M_rows = 65536
    sgemm_nt<<<dim3(2, 512, 1), 256>>>(
        rq, 0, 256, 8192,  pfused, 0, 256, 256,
        Wc1, 0, 512,  bc1, 0,
        pch, 0, 0, 1,  256, 512, 1.f, 0, 1);
    // 9) sigmoid gate + mean over m
    final_gate<<<8192, 256>>>(pch, pfused, wc2, bc2, out);
}